// round 2
// baseline (speedup 1.0000x reference)
#include <cuda_runtime.h>
#include <cstdint>

// Problem constants
#define BB 16
#define CC 256      // embedding dim (channel)
#define TT 4096     // time
#define KK 1024     // codebook size
#define BCT (16777216)          // B*C*T
#define NIDX (BB*TT)            // 65536
#define TM 64       // t per block
#define TKK 128     // k per k-tile
#define NBLK (BB * (TT/TM))     // 1024 blocks

// Device scratch (no dynamic allocation allowed)
__device__ float g_cbT[CC * KK];     // codebook transposed [D][K], 1 MB
__device__ float g_cbnorm[KK];       // ||e_k||^2 (fp32, sequential-d FMA)
__device__ float g_part[NBLK];       // per-block loss partials (deterministic reduce)

// ---------------------------------------------------------------------------
// Kernel A: transpose codebook -> g_cbT, compute norms (sequential fp32 FMA).
// ---------------------------------------------------------------------------
__global__ void vq_prep(const float* __restrict__ cb) {
    int gid = blockIdx.x * 256 + threadIdx.x;   // 0..65535
    #pragma unroll
    for (int r = 0; r < 4; r++) {
        int i = r * 65536 + gid;                 // 0..262143
        int k = i >> 8;                          // row
        int d = i & 255;                         // col
        g_cbT[d * KK + k] = cb[i];
    }
    if (gid < KK) {
        const float* row = cb + gid * CC;
        float s = 0.f;
        for (int d = 0; d < CC; d++) s = fmaf(row[d], row[d], s);  // sequential
        g_cbnorm[gid] = s;
    }
}

// ---------------------------------------------------------------------------
// Kernel B: main. One block = 64 consecutive t of one batch b.
// Register-blocked fp32 GEMM (4t x 8k per thread), strictly-sequential-d FMA
// per output (matches Eigen gebp / cublas sgemm accumulation order).
// Distance emulates reference fp32 expression: (||x||^2 + ||e||^2) - 2*(x.e)
// with lowest-index tiebreak -> bit-exact argmin vs reference.
// ---------------------------------------------------------------------------
__global__ __launch_bounds__(256, 2)
void vq_main(const float* __restrict__ x, float* __restrict__ out,
             int write_aux) {
    extern __shared__ float sm[];
    float* xs   = sm;            // [256][64]  fp32  (x tile, d-major)
    float* es   = sm + 16384;    // [32][128]        (codebook tile, d-major)
    float* nrm  = sm + 20480;    // [128]
    float* sa   = sm + 20608;    // [64]  ||x_t||^2
    int*   sidx = (int*)(sm + 20672);  // [64]
    float* red  = sm + 20736;    // [8]

    const int t0  = blockIdx.x * TM;
    const int b   = blockIdx.y;
    const int tid = threadIdx.x;
    const float* xb = x + (size_t)b * CC * TT;

    // ---- load x tile: xs[c][t] ; gmem already [c][t] so direct copy ----
    #pragma unroll
    for (int it = 0; it < 16; it++) {
        int i = it * 256 + tid;          // 4096 float4 jobs
        int c  = i >> 4;
        int t4 = (i & 15) << 2;
        float4 v = *(const float4*)(xb + (size_t)c * TT + t0 + t4);
        *(float4*)(xs + c * TM + t4) = v;
    }
    __syncthreads();

    // ---- per-t ||x||^2 (fp32; cross-k ordering is independent of its exact
    //      rounding, any fp32 value in the right binade works) ----
    if (tid < TM) {
        float s = 0.f;
        for (int d = 0; d < CC; d++) {
            float v = xs[d * TM + tid];
            s = fmaf(v, v, s);
        }
        sa[tid] = s;
    }

    const int tr = tid >> 4;   // 0..15 : owns t = tr*4 + i
    const int tc = tid & 15;   // 0..15 : owns k = k0 + tc*8 + j

    float bestd[4] = {3.4e38f, 3.4e38f, 3.4e38f, 3.4e38f};
    int   bestk[4] = {0, 0, 0, 0};

    float av[4];
    // sa ready after the barrier inside the kt loop below (first iteration)

    for (int kt = 0; kt < KK / TKK; kt++) {
        const int k0 = kt * TKK;
        __syncthreads();                       // protect nrm/es; also orders sa
        if (tid < TKK) nrm[tid] = g_cbnorm[k0 + tid];

        float acc[4][8];
        #pragma unroll
        for (int i = 0; i < 4; i++)
            #pragma unroll
            for (int j = 0; j < 8; j++) acc[i][j] = 0.f;

        for (int dt = 0; dt < 8; dt++) {
            __syncthreads();
            // stage es[dd][k] from g_cbT (coalesced, contiguous stores)
            #pragma unroll
            for (int it = 0; it < 4; it++) {
                int i  = it * 256 + tid;       // 1024 float4 jobs
                int dd = i >> 5;
                int k4 = (i & 31) << 2;
                *(float4*)(es + dd * TKK + k4) =
                    *(const float4*)(g_cbT + (size_t)((dt << 5) + dd) * KK + k0 + k4);
            }
            __syncthreads();

            #pragma unroll
            for (int d = 0; d < 32; d++) {
                const float4 xv = *(const float4*)(xs + ((dt << 5) + d) * TM + (tr << 2));
                const float4 e0 = *(const float4*)(es + d * TKK + (tc << 3));
                const float4 e1 = *(const float4*)(es + d * TKK + (tc << 3) + 4);
                const float xr[4] = {xv.x, xv.y, xv.z, xv.w};
                const float er[8] = {e0.x, e0.y, e0.z, e0.w, e1.x, e1.y, e1.z, e1.w};
                #pragma unroll
                for (int i = 0; i < 4; i++)
                    #pragma unroll
                    for (int j = 0; j < 8; j++)
                        acc[i][j] = fmaf(xr[i], er[j], acc[i][j]);  // sequential d
            }
        }

        // load per-t norms once (sa was written before first barrier)
        if (kt == 0) {
            #pragma unroll
            for (int i = 0; i < 4; i++) av[i] = sa[(tr << 2) + i];
        }

        // argmin update, emulating reference fp32 expression:
        // dist = (||x||^2 + ||e||^2) - 2*(x.e)    [2*s is exact]
        #pragma unroll
        for (int j = 0; j < 8; j++) {
            int k = k0 + (tc << 3) + j;
            float nb = nrm[(tc << 3) + j];
            #pragma unroll
            for (int i = 0; i < 4; i++) {
                float tmp  = av[i] + nb;             // rounds like reference
                float dist = tmp - 2.0f * acc[i][j]; // == RN(tmp - 2s)
                if (dist < bestd[i]) { bestd[i] = dist; bestk[i] = k; }
            }
        }
    }

    // ---- reduce argmin across the 16 tc lanes (lowest index on ties) ----
    #pragma unroll
    for (int i = 0; i < 4; i++) {
        float d = bestd[i];
        int   k = bestk[i];
        #pragma unroll
        for (int off = 8; off > 0; off >>= 1) {
            float od = __shfl_xor_sync(0xffffffffu, d, off, 16);
            int   ok = __shfl_xor_sync(0xffffffffu, k, off, 16);
            if (od < d || (od == d && ok < k)) { d = od; k = ok; }
        }
        if (tc == 0) sidx[(tr << 2) + i] = k;
    }
    __syncthreads();

    // ---- gather codebook rows, straight-through output, loss partial ----
    float lsum = 0.f;
    const size_t obase = (size_t)b * CC * TT + t0;
    #pragma unroll 4
    for (int it = 0; it < 16; it++) {
        int i  = it * 256 + tid;
        int c  = i >> 4;
        int t4 = (i & 15) << 2;
        float4 xv = *(const float4*)(xs + c * TM + t4);
        int i0 = sidx[t4 + 0], i1 = sidx[t4 + 1], i2 = sidx[t4 + 2], i3 = sidx[t4 + 3];
        const float* cbtc = g_cbT + (size_t)c * KK;
        float q0 = cbtc[i0], q1 = cbtc[i1], q2 = cbtc[i2], q3 = cbtc[i3];
        // mimic reference fp32 ops: diff = q - x ; out = x + diff ; loss += diff^2
        float d0 = q0 - xv.x, d1 = q1 - xv.y, d2 = q2 - xv.z, d3 = q3 - xv.w;
        lsum = fmaf(d0, d0, lsum);
        lsum = fmaf(d1, d1, lsum);
        lsum = fmaf(d2, d2, lsum);
        lsum = fmaf(d3, d3, lsum);
        float4 o;
        o.x = xv.x + d0; o.y = xv.y + d1; o.z = xv.z + d2; o.w = xv.w + d3;
        *(float4*)(out + obase + (size_t)c * TT + t4) = o;
    }

    // ---- block loss reduce (fixed order -> deterministic) ----
    #pragma unroll
    for (int off = 16; off > 0; off >>= 1)
        lsum += __shfl_xor_sync(0xffffffffu, lsum, off);
    if ((tid & 31) == 0) red[tid >> 5] = lsum;
    __syncthreads();
    if (tid == 0) {
        float s = 0.f;
        #pragma unroll
        for (int w = 0; w < 8; w++) s += red[w];
        g_part[blockIdx.y * gridDim.x + blockIdx.x] = s;
    }

    // ---- indices output (as float) ----
    if (write_aux && tid < TM) {
        out[(size_t)BCT + 1 + (size_t)b * TT + t0 + tid] = (float)sidx[tid];
    }
}

// ---------------------------------------------------------------------------
// Kernel C: deterministic final loss reduce.
// ---------------------------------------------------------------------------
__global__ void vq_finalize(float* __restrict__ out, int write_loss) {
    __shared__ float s[256];
    float v = 0.f;
    for (int i = threadIdx.x; i < NBLK; i += 256) v += g_part[i];
    s[threadIdx.x] = v;
    __syncthreads();
    for (int off = 128; off > 0; off >>= 1) {
        if (threadIdx.x < off) s[threadIdx.x] += s[threadIdx.x + off];
        __syncthreads();
    }
    if (threadIdx.x == 0 && write_loss) {
        out[BCT] = 1.25f * s[0] / 16777216.f;
    }
}

// ---------------------------------------------------------------------------
extern "C" void kernel_launch(void* const* d_in, const int* in_sizes, int n_in,
                              void* d_out, int out_size) {
    const float* x  = (const float*)d_in[0];   // [B, C, T] fp32
    const float* cb = (const float*)d_in[1];   // [K, D]   fp32
    float* out = (float*)d_out;

    const long long expected = (long long)BCT + 1 + NIDX;
    int write_aux = (out_size >= expected) ? 1 : 0;

    static int smem_set = 0;
    const int smem_bytes = (16384 + 4096 + 128 + 64 + 64 + 8) * 4;
    if (!smem_set) {
        cudaFuncSetAttribute(vq_main, cudaFuncAttributeMaxDynamicSharedMemorySize,
                             smem_bytes);
        smem_set = 1;
    }

    vq_prep<<<256, 256>>>(cb);
    vq_main<<<dim3(TT / TM, BB), 256, smem_bytes>>>(x, out, write_aux);
    vq_finalize<<<1, 256>>>(out, write_aux);
}

// round 8
// speedup vs baseline: 2.2743x; 2.2743x over previous
#include <cuda_runtime.h>
#include <cuda_bf16.h>
#include <cstdint>

#define BB 16
#define CC 256
#define TT 4096
#define KK 1024
#define BCT 16777216
#define NROWS 65536
#define WMARG 4.0e-4f
#define FINF 3.4e38f

// ---------------- device scratch ----------------
__device__ __align__(16) __nv_bfloat16 g_Ebf[KK * CC];  // bf16 codebook [k][d]
__device__ float g_cbnorm[KK];
__device__ float g_part[1024];
__device__ int   g_idx[NROWS];
__device__ int   g_cand[NROWS * 8];
__device__ unsigned char g_ccnt[NROWS];
__device__ int   g_flag[NROWS];
__device__ int   g_nflag;

// ---------------- helpers ----------------
__device__ __forceinline__ unsigned su32(const void* p) {
    unsigned a; asm("{ .reg .u64 t; cvta.to.shared.u64 t, %1; cvt.u32.u64 %0, t; }" : "=r"(a) : "l"(p)); return a;
}
__device__ __forceinline__ void ldm4(unsigned* r, unsigned addr) {
    asm volatile("ldmatrix.sync.aligned.m8n8.x4.shared.b16 {%0,%1,%2,%3}, [%4];"
        : "=r"(r[0]), "=r"(r[1]), "=r"(r[2]), "=r"(r[3]) : "r"(addr));
}
__device__ __forceinline__ void mma16816(float* c, const unsigned* a, const unsigned* b) {
    asm volatile("mma.sync.aligned.m16n8k16.row.col.f32.bf16.bf16.f32 "
        "{%0,%1,%2,%3}, {%4,%5,%6,%7}, {%8,%9}, {%0,%1,%2,%3};"
        : "+f"(c[0]), "+f"(c[1]), "+f"(c[2]), "+f"(c[3])
        : "r"(a[0]), "r"(a[1]), "r"(a[2]), "r"(a[3]), "r"(b[0]), "r"(b[1]));
}
__device__ __forceinline__ void top4_ins(float d, int k, float* td, int* tk) {
    if (d < td[3]) {
        td[3] = d; tk[3] = k;
        if (td[3] < td[2]) { float t = td[2]; td[2] = td[3]; td[3] = t; int u = tk[2]; tk[2] = tk[3]; tk[3] = u; }
        if (td[2] < td[1]) { float t = td[1]; td[1] = td[2]; td[2] = t; int u = tk[1]; tk[1] = tk[2]; tk[2] = u; }
        if (td[1] < td[0]) { float t = td[0]; td[0] = td[1]; td[1] = t; int u = tk[0]; tk[0] = tk[1]; tk[1] = u; }
    }
}

// smem layout (bytes) for vq_cand
#define PITCHB 528                 // 264 bf16 per row
#define SM_AHI  0                  // 128*528 = 67584
#define SM_ALO  67584              // 67584
#define SM_B    135168             // 2 x (64*528=33792) = 67584
#define SM_NRM  202752             // 4096
#define SM_TOT  206848

// ---------------------------------------------------------------------------
// prep: bf16 codebook + norms (sequential fp32 FMA) + flag reset
// ---------------------------------------------------------------------------
__global__ void vq_prep(const float* __restrict__ cb) {
    int gid = blockIdx.x * 256 + threadIdx.x;
    #pragma unroll
    for (int r = 0; r < 4; r++) {
        int i = r * 65536 + gid;
        g_Ebf[i] = __float2bfloat16(cb[i]);
    }
    if (gid < KK) {
        const float* row = cb + gid * CC;
        float s = 0.f;
        #pragma unroll 8
        for (int d = 0; d < CC; d++) s = fmaf(row[d], row[d], s);
        g_cbnorm[gid] = s;
    }
    if (gid == 0) g_nflag = 0;
}

// ---------------------------------------------------------------------------
// candidate kernel: warp-mma bf16 GEMM (hi/lo split) + top-4 candidate argmin
// 512 CTAs x 512 threads; CTA = 128 rows of one batch
// ---------------------------------------------------------------------------
__global__ __launch_bounds__(512, 1)
void vq_cand(const float* __restrict__ x) {
    extern __shared__ char smem[];
    const unsigned smb = su32(smem);
    const int tid = threadIdx.x, wid = tid >> 5, l = tid & 31;
    const int wt = wid >> 1, wk = wid & 1;
    const int b = blockIdx.x >> 5;
    const int t0 = (blockIdx.x & 31) * 128;
    const float* xb = x + (size_t)b * CC * TT + t0;

    // ---- norms to smem ----
    float* nrm_s = (float*)(smem + SM_NRM);
    #pragma unroll
    for (int r = 0; r < 2; r++) nrm_s[r * 512 + tid] = g_cbnorm[r * 512 + tid];

    // ---- build A tiles (hi/lo bf16, row-major [t][d], pitch 264 bf16) ----
    {
        float* scr = (float*)(smem + SM_B + 33792);   // buffer1 as fp32 scratch [64][132]
        for (int pass = 0; pass < 4; pass++) {
            const int c0 = pass * 64;
            __syncthreads();
            #pragma unroll
            for (int it = 0; it < 4; it++) {
                int j = it * 512 + tid;               // 2048 float4 jobs
                int cl = j >> 5, t4 = (j & 31) << 2;
                *(float4*)(scr + cl * 132 + t4) =
                    *(const float4*)(xb + (size_t)(c0 + cl) * TT + t4);
            }
            __syncthreads();
            const int t = tid >> 2, u4 = tid & 3;     // t 0..127, 16 c's per thread
            unsigned hw[8], lw[8];
            #pragma unroll
            for (int v = 0; v < 8; v++) {
                int c = u4 * 16 + 2 * v;
                float a0 = scr[c * 132 + t], a1 = scr[(c + 1) * 132 + t];
                __nv_bfloat16 h0 = __float2bfloat16(a0), h1 = __float2bfloat16(a1);
                __nv_bfloat16 l0 = __float2bfloat16(a0 - __bfloat162float(h0));
                __nv_bfloat16 l1 = __float2bfloat16(a1 - __bfloat162float(h1));
                hw[v] = ((unsigned)__bfloat16_as_ushort(h1) << 16) | __bfloat16_as_ushort(h0);
                lw[v] = ((unsigned)__bfloat16_as_ushort(l1) << 16) | __bfloat16_as_ushort(l0);
            }
            unsigned abyte = (unsigned)(t * PITCHB + (c0 + u4 * 16) * 2);
            unsigned ah = smb + SM_AHI + abyte, al = smb + SM_ALO + abyte;
            asm volatile("st.shared.v4.b32 [%0], {%1,%2,%3,%4};" :: "r"(ah), "r"(hw[0]), "r"(hw[1]), "r"(hw[2]), "r"(hw[3]) : "memory");
            asm volatile("st.shared.v4.b32 [%0], {%1,%2,%3,%4};" :: "r"(ah + 16), "r"(hw[4]), "r"(hw[5]), "r"(hw[6]), "r"(hw[7]) : "memory");
            asm volatile("st.shared.v4.b32 [%0], {%1,%2,%3,%4};" :: "r"(al), "r"(lw[0]), "r"(lw[1]), "r"(lw[2]), "r"(lw[3]) : "memory");
            asm volatile("st.shared.v4.b32 [%0], {%1,%2,%3,%4};" :: "r"(al + 16), "r"(lw[4]), "r"(lw[5]), "r"(lw[6]), "r"(lw[7]) : "memory");
        }
        __syncthreads();
    }

    // ---- preload B chunk 0 (64 codes x 256 d) into buffer 0 ----
    {
        #pragma unroll
        for (int it = 0; it < 4; it++) {
            int j = it * 512 + tid;                    // 2048 uint4 jobs
            int code = j >> 5, g = j & 31;
            uint4 v = *(const uint4*)(g_Ebf + (size_t)code * CC + g * 8);
            *(uint4*)(smem + SM_B + code * PITCHB + g * 16) = v;
        }
        __syncthreads();
    }

    // ---- per-thread mma addresses ----
    const unsigned row_a = (unsigned)(wt * 16 + (l & 7) + ((l >> 3) & 1) * 8);
    const unsigned koff_a = (unsigned)(((l >> 4) & 1) * 8);
    const unsigned ahi_base = smb + SM_AHI + row_a * PITCHB + koff_a * 2;
    const unsigned alo_base = smb + SM_ALO + row_a * PITCHB + koff_a * 2;
    const unsigned nrow = (unsigned)((l >> 4) * 8 + (l & 7));
    const unsigned kcol = (unsigned)(((l >> 3) & 1) * 8);
    const unsigned b_thr = (unsigned)((wk * 32 + nrow) * PITCHB + kcol * 2);

    float c[4][4];
    #pragma unroll
    for (int nt = 0; nt < 4; nt++)
        #pragma unroll
        for (int q = 0; q < 4; q++) c[nt][q] = 0.f;

    float t4d0[4] = {FINF, FINF, FINF, FINF}, t4d1[4] = {FINF, FINF, FINF, FINF};
    int   t4k0[4] = {0, 0, 0, 0},             t4k1[4] = {0, 0, 0, 0};

    for (int kc = 0; kc < 16; kc++) {
        // prefetch next B chunk into regs
        uint4 pf[4];
        if (kc < 15) {
            #pragma unroll
            for (int it = 0; it < 4; it++) {
                int j = it * 512 + tid;
                int code = j >> 5, g = j & 31;
                pf[it] = *(const uint4*)(g_Ebf + (size_t)((kc + 1) * 64 + code) * CC + g * 8);
            }
        }

        const unsigned bbase = smb + SM_B + (kc & 1) * 33792 + b_thr;
        #pragma unroll 4
        for (int s = 0; s < 16; s++) {
            unsigned ah[4], al[4], bb[4], bb2[4];
            ldm4(ah, ahi_base + s * 32);
            ldm4(al, alo_base + s * 32);
            ldm4(bb,  bbase + s * 32);
            ldm4(bb2, bbase + 16 * PITCHB + s * 32);
            mma16816(c[0], ah, bb);      mma16816(c[0], al, bb);
            mma16816(c[1], ah, bb + 2);  mma16816(c[1], al, bb + 2);
            mma16816(c[2], ah, bb2);     mma16816(c[2], al, bb2);
            mma16816(c[3], ah, bb2 + 2); mma16816(c[3], al, bb2 + 2);
        }

        // epilogue: fine dist + top4 update; reset accums
        #pragma unroll
        for (int nt = 0; nt < 4; nt++) {
            const int kbase = kc * 64 + wk * 32 + nt * 8 + (l & 3) * 2;
            #pragma unroll
            for (int q = 0; q < 4; q++) {
                int k = kbase + (q & 1);
                float dist = fmaf(-2.f, c[nt][q], nrm_s[k]);
                if (q < 2) top4_ins(dist, k, t4d0, t4k0);
                else       top4_ins(dist, k, t4d1, t4k1);
                c[nt][q] = 0.f;
            }
        }

        __syncthreads();
        if (kc < 15) {
            #pragma unroll
            for (int it = 0; it < 4; it++) {
                int j = it * 512 + tid;
                int code = j >> 5, g = j & 31;
                *(uint4*)(smem + SM_B + ((kc + 1) & 1) * 33792 + code * PITCHB + g * 16) = pf[it];
            }
        }
        __syncthreads();
    }

    // ---- dump per-thread top4 lists to smem (overlay on B buffer 0) ----
    float* cd = (float*)(smem + SM_B);          // [128][33]
    int*   ck = (int*)(smem + SM_B + 16896);    // [128][33]
    {
        const int r0 = wt * 16 + (l >> 2), r1 = r0 + 8;
        const int slot = (wk * 4 + (l & 3)) * 4;
        #pragma unroll
        for (int j = 0; j < 4; j++) {
            cd[r0 * 33 + slot + j] = t4d0[j]; ck[r0 * 33 + slot + j] = t4k0[j];
            cd[r1 * 33 + slot + j] = t4d1[j]; ck[r1 * 33 + slot + j] = t4k1[j];
        }
    }
    __syncthreads();

    // ---- per-row merge (threads 0..127) ----
    if (tid < 128) {
        const int row = b * TT + t0 + tid;
        float bd = FINF; int bk = 0x7fffffff;
        #pragma unroll 8
        for (int e = 0; e < 32; e++) {
            float d = cd[tid * 33 + e]; int k = ck[tid * 33 + e];
            if (d < bd || (d == bd && k < bk)) { bd = d; bk = k; }
        }
        const float thr = bd + WMARG;
        int m = 0, ovf = 0;
        #pragma unroll 8
        for (int e = 0; e < 32; e++) {
            float d = cd[tid * 33 + e];
            if (d <= thr) {
                if (m < 8) g_cand[row * 8 + m] = ck[tid * 33 + e];
                m++;
                if ((e & 3) == 3) ovf = 1;   // a thread's 4th entry within margin
            }
        }
        if (m > 8) ovf = 1;
        g_idx[row] = bk;
        if (m > 1 || ovf) {
            g_ccnt[row] = ovf ? 255 : (unsigned char)m;
            int p = atomicAdd(&g_nflag, 1);
            g_flag[p] = row;
        }
    }
}

// ---------------------------------------------------------------------------
// exact rescore of flagged rows (bit-exact grid argmin; R2-validated recipe)
// ---------------------------------------------------------------------------
__global__ void vq_rescore(const float* __restrict__ x, const float* __restrict__ cb) {
    int gtid = blockIdx.x * 128 + threadIdx.x;
    int nf = g_nflag;
    for (int i = gtid; i < nf; i += 16384) {
        int row = g_flag[i];
        int bq = row >> 12, t = row & 4095;
        const float* xp = x + (size_t)bq * CC * TT + t;
        float a = 0.f;
        #pragma unroll 8
        for (int d = 0; d < CC; d++) {
            float v = xp[(size_t)d * TT];
            a = fmaf(v, v, a);
        }
        float bd = FINF; int bk = 0x7fffffff;
        int m = g_ccnt[row];
        if (m == 255) {
            for (int k = 0; k < KK; k++) {
                const float* e = cb + (size_t)k * CC;
                float s = 0.f;
                #pragma unroll 8
                for (int d = 0; d < CC; d++) s = fmaf(xp[(size_t)d * TT], e[d], s);
                float dist = (a + g_cbnorm[k]) - 2.0f * s;
                if (dist < bd || (dist == bd && k < bk)) { bd = dist; bk = k; }
            }
        } else {
            for (int ci = 0; ci < m; ci++) {
                int k = g_cand[row * 8 + ci];
                const float* e = cb + (size_t)k * CC;
                float s = 0.f;
                #pragma unroll 8
                for (int d = 0; d < CC; d++) s = fmaf(xp[(size_t)d * TT], e[d], s);
                float dist = (a + g_cbnorm[k]) - 2.0f * s;
                if (dist < bd || (dist == bd && k < bk)) { bd = dist; bk = k; }
            }
        }
        g_idx[row] = bk;
    }
}

// ---------------------------------------------------------------------------
// output kernel: straight-through quantized + loss partials + indices
// ---------------------------------------------------------------------------
__global__ __launch_bounds__(256, 1)
void vq_out(const float* __restrict__ x, const float* __restrict__ cb,
            float* __restrict__ out, int write_aux) {
    extern __shared__ float sm[];
    float* xs  = sm;               // [256][64]          = 16384 floats
    float* qs  = sm + 16384;       // [64][260]          = 16640 floats
    float* red = sm + 16384 + 16640;   // [8]
    int* kidx  = (int*)(red + 8);  // [64]  (smem total = 16384+16640+8+64 floats)
    const int t0 = blockIdx.x * 64, b = blockIdx.y, tid = threadIdx.x;
    const float* xb = x + (size_t)b * CC * TT;

    #pragma unroll
    for (int it = 0; it < 16; it++) {
        int i = it * 256 + tid, c = i >> 4, t4 = (i & 15) << 2;
        *(float4*)(xs + c * 64 + t4) = *(const float4*)(xb + (size_t)c * TT + t0 + t4);
    }
    if (tid < 64) kidx[tid] = g_idx[b * TT + t0 + tid];
    __syncthreads();
    #pragma unroll
    for (int it = 0; it < 16; it++) {
        int i = it * 256 + tid, t = i >> 6, f4 = (i & 63) << 2;
        *(float4*)(qs + t * 260 + f4) = *(const float4*)(cb + (size_t)kidx[t] * CC + f4);
    }
    __syncthreads();

    float lsum = 0.f;
    const size_t obase = (size_t)b * CC * TT + t0;
    #pragma unroll 4
    for (int it = 0; it < 16; it++) {
        int i = it * 256 + tid, c = i >> 4, t4 = (i & 15) << 2;
        float4 xv = *(float4*)(xs + c * 64 + t4);
        float q0 = qs[(t4 + 0) * 260 + c], q1 = qs[(t4 + 1) * 260 + c];
        float q2 = qs[(t4 + 2) * 260 + c], q3 = qs[(t4 + 3) * 260 + c];
        float d0 = q0 - xv.x, d1 = q1 - xv.y, d2 = q2 - xv.z, d3 = q3 - xv.w;
        lsum = fmaf(d0, d0, lsum); lsum = fmaf(d1, d1, lsum);
        lsum = fmaf(d2, d2, lsum); lsum = fmaf(d3, d3, lsum);
        float4 o; o.x = xv.x + d0; o.y = xv.y + d1; o.z = xv.z + d2; o.w = xv.w + d3;
        *(float4*)(out + obase + (size_t)c * TT + t4) = o;
    }
    #pragma unroll
    for (int off = 16; off > 0; off >>= 1)
        lsum += __shfl_xor_sync(0xffffffffu, lsum, off);
    if ((tid & 31) == 0) red[tid >> 5] = lsum;
    __syncthreads();
    if (tid == 0) {
        float s = 0.f;
        #pragma unroll
        for (int w = 0; w < 8; w++) s += red[w];
        g_part[blockIdx.y * gridDim.x + blockIdx.x] = s;
    }
    if (write_aux && tid < 64)
        out[(size_t)BCT + 1 + (size_t)b * TT + t0 + tid] = (float)kidx[tid];
}

__global__ void vq_finalize(float* __restrict__ out, int write_loss) {
    __shared__ float s[256];
    float v = 0.f;
    for (int i = threadIdx.x; i < 1024; i += 256) v += g_part[i];
    s[threadIdx.x] = v;
    __syncthreads();
    for (int off = 128; off > 0; off >>= 1) {
        if (threadIdx.x < off) s[threadIdx.x] += s[threadIdx.x + off];
        __syncthreads();
    }
    if (threadIdx.x == 0 && write_loss) out[BCT] = 1.25f * s[0] / 16777216.f;
}

// ---------------------------------------------------------------------------
extern "C" void kernel_launch(void* const* d_in, const int* in_sizes, int n_in,
                              void* d_out, int out_size) {
    const float* x  = (const float*)d_in[0];
    const float* cb = (const float*)d_in[1];
    float* out = (float*)d_out;
    const long long expected = (long long)BCT + 1 + NROWS;
    int write_aux = (out_size >= expected) ? 1 : 0;

    static int attr_set = 0;
    const int out_smem = (16384 + 16640 + 8 + 64) * 4;   // kidx = 64 ints
    if (!attr_set) {
        cudaFuncSetAttribute(vq_cand, cudaFuncAttributeMaxDynamicSharedMemorySize, SM_TOT);
        cudaFuncSetAttribute(vq_out,  cudaFuncAttributeMaxDynamicSharedMemorySize, out_smem);
        attr_set = 1;
    }

    vq_prep<<<256, 256>>>(cb);
    vq_cand<<<512, 512, SM_TOT>>>(x);
    vq_rescore<<<128, 128>>>(x, cb);
    vq_out<<<dim3(64, 16), 256, out_smem>>>(x, cb, out, write_aux);
    vq_finalize<<<1, 256>>>(out, write_aux);
}

// round 11
// speedup vs baseline: 2.7391x; 1.2044x over previous
#include <cuda_runtime.h>
#include <cuda_bf16.h>
#include <cstdint>

#define BB 16
#define CC 256
#define TT 4096
#define KK 1024
#define BCT 16777216
#define NROWS 65536
#define WMARG 5.0e-4f
#define FINF 3.4e38f

// ---------------- device scratch ----------------
__device__ __align__(16) __nv_bfloat16 g_Ebf[KK * CC];  // bf16 codebook [k][d]
__device__ float g_cbnorm[KK];
__device__ float g_part[1024];
__device__ int   g_idx[NROWS];
__device__ int   g_cand[NROWS * 8];
__device__ unsigned char g_ccnt[NROWS];
__device__ int   g_flag[NROWS];
__device__ int   g_nflag;

// ---------------- helpers ----------------
__device__ __forceinline__ unsigned su32(const void* p) {
    unsigned a; asm("{ .reg .u64 t; cvta.to.shared.u64 t, %1; cvt.u32.u64 %0, t; }" : "=r"(a) : "l"(p)); return a;
}
__device__ __forceinline__ void ldm4(unsigned* r, unsigned addr) {
    asm volatile("ldmatrix.sync.aligned.m8n8.x4.shared.b16 {%0,%1,%2,%3}, [%4];"
        : "=r"(r[0]), "=r"(r[1]), "=r"(r[2]), "=r"(r[3]) : "r"(addr));
}
__device__ __forceinline__ void mma16816(float* c, const unsigned* a, const unsigned* b) {
    asm volatile("mma.sync.aligned.m16n8k16.row.col.f32.bf16.bf16.f32 "
        "{%0,%1,%2,%3}, {%4,%5,%6,%7}, {%8,%9}, {%0,%1,%2,%3};"
        : "+f"(c[0]), "+f"(c[1]), "+f"(c[2]), "+f"(c[3])
        : "r"(a[0]), "r"(a[1]), "r"(a[2]), "r"(a[3]), "r"(b[0]), "r"(b[1]));
}
__device__ __forceinline__ void cpasync16(unsigned dst, const void* src) {
    asm volatile("cp.async.cg.shared.global [%0], [%1], 16;" :: "r"(dst), "l"(src) : "memory");
}
#define CP_COMMIT() asm volatile("cp.async.commit_group;" ::: "memory")
#define CP_WAIT1()  asm volatile("cp.async.wait_group 1;" ::: "memory")
#define CP_WAIT0()  asm volatile("cp.async.wait_group 0;" ::: "memory")

__device__ __forceinline__ void top4_ins(float d, int k, float* td, int* tk) {
    if (d < td[3]) {
        td[3] = d; tk[3] = k;
        if (td[3] < td[2]) { float t = td[2]; td[2] = td[3]; td[3] = t; int u = tk[2]; tk[2] = tk[3]; tk[3] = u; }
        if (td[2] < td[1]) { float t = td[1]; td[1] = td[2]; td[2] = t; int u = tk[1]; tk[1] = tk[2]; tk[2] = u; }
        if (td[1] < td[0]) { float t = td[0]; td[0] = td[1]; td[1] = t; int u = tk[0]; tk[0] = tk[1]; tk[1] = u; }
    }
}

// smem layout (bytes) for vq_cand
#define PITCHB 528                 // 264 bf16 per row
#define SM_A    0                  // 128*528 = 67584 (single bf16 A)
#define SM_B    67584              // 2 x (128*528=67584) = 135168
#define SM_NRM  202752             // 4096
#define SM_TOT  206848

// ---------------------------------------------------------------------------
// prep: bf16 codebook + norms (sequential fp32 FMA) + flag reset
// ---------------------------------------------------------------------------
__global__ void vq_prep(const float* __restrict__ cb) {
    int gid = blockIdx.x * 256 + threadIdx.x;
    #pragma unroll
    for (int r = 0; r < 4; r++) {
        int i = r * 65536 + gid;
        g_Ebf[i] = __float2bfloat16(cb[i]);
    }
    if (gid < KK) {
        const float* row = cb + gid * CC;
        float s = 0.f;
        #pragma unroll 8
        for (int d = 0; d < CC; d++) s = fmaf(row[d], row[d], s);
        g_cbnorm[gid] = s;
    }
    if (gid == 0) g_nflag = 0;
}

// ---------------------------------------------------------------------------
// candidate kernel: single-bf16 warp-mma GEMM + top-4 candidate argmin
// 512 CTAs x 512 threads; CTA = 128 rows; warp tile 16t x 64 codes;
// B in 128-code chunks, cp.async double-buffered.
// ---------------------------------------------------------------------------
__global__ __launch_bounds__(512, 1)
void vq_cand(const float* __restrict__ x) {
    extern __shared__ char smem[];
    const unsigned smb = su32(smem);
    const int tid = threadIdx.x, wid = tid >> 5, l = tid & 31;
    const int wt = wid >> 1, wk = wid & 1;
    const int b = blockIdx.x >> 5;
    const int t0 = (blockIdx.x & 31) * 128;
    const float* xb = x + (size_t)b * CC * TT + t0;

    // ---- norms to smem ----
    float* nrm_s = (float*)(smem + SM_NRM);
    #pragma unroll
    for (int r = 0; r < 2; r++) nrm_s[r * 512 + tid] = g_cbnorm[r * 512 + tid];

    // ---- build A tile (bf16, row-major [t][d], pitch 264 bf16) ----
    {
        float* scr = (float*)(smem + SM_B);           // B0 as fp32 scratch [64][132]
        for (int pass = 0; pass < 4; pass++) {
            const int c0 = pass * 64;
            __syncthreads();
            #pragma unroll
            for (int it = 0; it < 4; it++) {
                int j = it * 512 + tid;               // 2048 float4 jobs
                int cl = j >> 5, t4 = (j & 31) << 2;
                *(float4*)(scr + cl * 132 + t4) =
                    *(const float4*)(xb + (size_t)(c0 + cl) * TT + t4);
            }
            __syncthreads();
            const int t = tid >> 2, u4 = tid & 3;     // t 0..127, 16 c's per thread
            unsigned hw[8];
            #pragma unroll
            for (int v = 0; v < 8; v++) {
                int c = u4 * 16 + 2 * v;
                float a0 = scr[c * 132 + t], a1 = scr[(c + 1) * 132 + t];
                __nv_bfloat16 h0 = __float2bfloat16(a0), h1 = __float2bfloat16(a1);
                hw[v] = ((unsigned)__bfloat16_as_ushort(h1) << 16) | __bfloat16_as_ushort(h0);
            }
            unsigned ah = smb + SM_A + (unsigned)(t * PITCHB + (c0 + u4 * 16) * 2);
            asm volatile("st.shared.v4.b32 [%0], {%1,%2,%3,%4};" :: "r"(ah), "r"(hw[0]), "r"(hw[1]), "r"(hw[2]), "r"(hw[3]) : "memory");
            asm volatile("st.shared.v4.b32 [%0], {%1,%2,%3,%4};" :: "r"(ah + 16), "r"(hw[4]), "r"(hw[5]), "r"(hw[6]), "r"(hw[7]) : "memory");
        }
        __syncthreads();
    }

    // ---- cp.async chunk 0 (128 codes x 256 d) into B0 ----
    {
        #pragma unroll
        for (int it = 0; it < 8; it++) {
            int j = it * 512 + tid;                    // 4096 x 16B jobs
            int code = j >> 5, g = j & 31;
            cpasync16(smb + SM_B + (unsigned)(code * PITCHB + g * 16),
                      g_Ebf + (size_t)code * CC + g * 8);
        }
        CP_COMMIT();
    }

    // ---- per-thread mma addresses ----
    const unsigned row_a = (unsigned)(wt * 16 + (l & 7) + ((l >> 3) & 1) * 8);
    const unsigned koff_a = (unsigned)(((l >> 4) & 1) * 8);
    const unsigned a_base = smb + SM_A + row_a * PITCHB + koff_a * 2;
    const unsigned nrow = (unsigned)((l >> 4) * 8 + (l & 7));
    const unsigned kcol = (unsigned)(((l >> 3) & 1) * 8);
    const unsigned b_thr = (unsigned)((wk * 64 + nrow) * PITCHB + kcol * 2);

    float c[8][4];
    #pragma unroll
    for (int nt = 0; nt < 8; nt++)
        #pragma unroll
        for (int q = 0; q < 4; q++) c[nt][q] = 0.f;

    float t4d0[4] = {FINF, FINF, FINF, FINF}, t4d1[4] = {FINF, FINF, FINF, FINF};
    int   t4k0[4] = {0, 0, 0, 0},             t4k1[4] = {0, 0, 0, 0};

    for (int kc = 0; kc < 8; kc++) {
        // issue next chunk into other buffer
        if (kc < 7) {
            #pragma unroll
            for (int it = 0; it < 8; it++) {
                int j = it * 512 + tid;
                int code = j >> 5, g = j & 31;
                cpasync16(smb + SM_B + (unsigned)(((kc + 1) & 1) * 67584 + code * PITCHB + g * 16),
                          g_Ebf + (size_t)((kc + 1) * 128 + code) * CC + g * 8);
            }
            CP_COMMIT();
            CP_WAIT1();
        } else {
            CP_WAIT0();
        }
        __syncthreads();

        const unsigned bbase = smb + SM_B + (kc & 1) * 67584 + b_thr;
        #pragma unroll
        for (int s = 0; s < 16; s++) {
            unsigned a[4], b0[4], b1[4], b2[4], b3[4];
            ldm4(a, a_base + s * 32);
            ldm4(b0, bbase + s * 32);
            ldm4(b1, bbase + 16 * PITCHB + s * 32);
            ldm4(b2, bbase + 32 * PITCHB + s * 32);
            ldm4(b3, bbase + 48 * PITCHB + s * 32);
            mma16816(c[0], a, b0); mma16816(c[1], a, b0 + 2);
            mma16816(c[2], a, b1); mma16816(c[3], a, b1 + 2);
            mma16816(c[4], a, b2); mma16816(c[5], a, b2 + 2);
            mma16816(c[6], a, b3); mma16816(c[7], a, b3 + 2);
        }

        // epilogue: fine dist + top4 update; reset accums
        #pragma unroll
        for (int nt = 0; nt < 8; nt++) {
            const int kbase = kc * 128 + wk * 64 + nt * 8 + (l & 3) * 2;
            #pragma unroll
            for (int q = 0; q < 4; q++) {
                int k = kbase + (q & 1);
                float dist = fmaf(-2.f, c[nt][q], nrm_s[k]);
                if (q < 2) top4_ins(dist, k, t4d0, t4k0);
                else       top4_ins(dist, k, t4d1, t4k1);
                c[nt][q] = 0.f;
            }
        }
        __syncthreads();
    }

    // ---- dump per-thread top4 lists to smem (overlay on B buffer 0) ----
    float* cd = (float*)(smem + SM_B);          // [128][33]
    int*   ck = (int*)(smem + SM_B + 16896);    // [128][33]
    {
        const int r0 = wt * 16 + (l >> 2), r1 = r0 + 8;
        const int slot = (wk * 4 + (l & 3)) * 4;
        #pragma unroll
        for (int j = 0; j < 4; j++) {
            cd[r0 * 33 + slot + j] = t4d0[j]; ck[r0 * 33 + slot + j] = t4k0[j];
            cd[r1 * 33 + slot + j] = t4d1[j]; ck[r1 * 33 + slot + j] = t4k1[j];
        }
    }
    __syncthreads();

    // ---- per-row merge (threads 0..127) ----
    if (tid < 128) {
        const int row = b * TT + t0 + tid;
        float bd = FINF; int bk = 0x7fffffff;
        #pragma unroll 8
        for (int e = 0; e < 32; e++) {
            float d = cd[tid * 33 + e]; int k = ck[tid * 33 + e];
            if (d < bd || (d == bd && k < bk)) { bd = d; bk = k; }
        }
        const float thr = bd + WMARG;
        int m = 0, ovf = 0;
        #pragma unroll 8
        for (int e = 0; e < 32; e++) {
            float d = cd[tid * 33 + e];
            if (d <= thr) {
                if (m < 8) g_cand[row * 8 + m] = ck[tid * 33 + e];
                m++;
                if ((e & 3) == 3) ovf = 1;   // a thread's 4th entry within margin
            }
        }
        if (m > 8) ovf = 1;
        g_idx[row] = bk;
        if (m > 1 || ovf) {
            g_ccnt[row] = ovf ? 255 : (unsigned char)m;
            int p = atomicAdd(&g_nflag, 1);
            g_flag[p] = row;
        }
    }
}

// ---------------------------------------------------------------------------
// exact rescore of flagged rows (bit-exact grid argmin; R2-validated recipe)
// ---------------------------------------------------------------------------
__global__ void vq_rescore(const float* __restrict__ x, const float* __restrict__ cb) {
    int gtid = blockIdx.x * 128 + threadIdx.x;
    int nf = g_nflag;
    for (int i = gtid; i < nf; i += 16384) {
        int row = g_flag[i];
        int bq = row >> 12, t = row & 4095;
        const float* xp = x + (size_t)bq * CC * TT + t;
        float a = 0.f;
        #pragma unroll 8
        for (int d = 0; d < CC; d++) {
            float v = xp[(size_t)d * TT];
            a = fmaf(v, v, a);
        }
        float bd = FINF; int bk = 0x7fffffff;
        int m = g_ccnt[row];
        if (m == 255) {
            for (int k = 0; k < KK; k++) {
                const float* e = cb + (size_t)k * CC;
                float s = 0.f;
                #pragma unroll 8
                for (int d = 0; d < CC; d++) s = fmaf(xp[(size_t)d * TT], e[d], s);
                float dist = (a + g_cbnorm[k]) - 2.0f * s;
                if (dist < bd || (dist == bd && k < bk)) { bd = dist; bk = k; }
            }
        } else {
            for (int ci = 0; ci < m; ci++) {
                int k = g_cand[row * 8 + ci];
                const float* e = cb + (size_t)k * CC;
                float s = 0.f;
                #pragma unroll 8
                for (int d = 0; d < CC; d++) s = fmaf(xp[(size_t)d * TT], e[d], s);
                float dist = (a + g_cbnorm[k]) - 2.0f * s;
                if (dist < bd || (dist == bd && k < bk)) { bd = dist; bk = k; }
            }
        }
        g_idx[row] = bk;
    }
}

// ---------------------------------------------------------------------------
// output kernel: straight-through quantized + loss partials + indices.
// qsT[c][t] pitch 65 (scalar access only -> no alignment constraint).
// Reads qsT[c*65 + t]: within a warp t is consecutive -> conflict-free.
// ---------------------------------------------------------------------------
#define QTP 65
__global__ __launch_bounds__(256, 1)
void vq_out(const float* __restrict__ x, const float* __restrict__ cb,
            float* __restrict__ out, int write_aux) {
    extern __shared__ float sm[];
    float* qsT = sm;                      // [256][65]
    float* red = sm + CC * QTP;           // [8]
    int* kidx  = (int*)(red + 8);         // [64]
    const int t0 = blockIdx.x * 64, b = blockIdx.y, tid = threadIdx.x;
    const float* xb = x + (size_t)b * CC * TT + t0;
    float* ob = out + (size_t)b * CC * TT + t0;

    if (tid < 64) kidx[tid] = g_idx[b * TT + t0 + tid];
    __syncthreads();
    // gather codebook rows into qsT[c][t] (float4 global read, scalar smem writes)
    #pragma unroll
    for (int it = 0; it < 16; it++) {
        int i = it * 256 + tid, t = i >> 6, f4 = (i & 63) << 2;
        float4 v = *(const float4*)(cb + (size_t)kidx[t] * CC + f4);
        qsT[(f4 + 0) * QTP + t] = v.x;
        qsT[(f4 + 1) * QTP + t] = v.y;
        qsT[(f4 + 2) * QTP + t] = v.z;
        qsT[(f4 + 3) * QTP + t] = v.w;
    }
    __syncthreads();

    // main loop: thread job = (t, 4 consecutive c); warp = 32 consecutive t
    float lsum = 0.f;
    #pragma unroll 4
    for (int it = 0; it < 16; it++) {
        int j = it * 256 + tid;
        int t = j & 63, cg = (j >> 6) << 2;
        #pragma unroll
        for (int u = 0; u < 4; u++) {
            int c = cg + u;
            float xv = xb[(size_t)c * TT + t];
            float q  = qsT[c * QTP + t];
            float d  = q - xv;
            lsum = fmaf(d, d, lsum);
            ob[(size_t)c * TT + t] = xv + d;
        }
    }
    #pragma unroll
    for (int off = 16; off > 0; off >>= 1)
        lsum += __shfl_xor_sync(0xffffffffu, lsum, off);
    if ((tid & 31) == 0) red[tid >> 5] = lsum;
    __syncthreads();
    if (tid == 0) {
        float s = 0.f;
        #pragma unroll
        for (int w = 0; w < 8; w++) s += red[w];
        g_part[blockIdx.y * gridDim.x + blockIdx.x] = s;
    }
    if (write_aux && tid < 64)
        out[(size_t)BCT + 1 + (size_t)b * TT + t0 + tid] = (float)kidx[tid];
}

__global__ void vq_finalize(float* __restrict__ out, int write_loss) {
    __shared__ float s[256];
    float v = 0.f;
    for (int i = threadIdx.x; i < 1024; i += 256) v += g_part[i];
    s[threadIdx.x] = v;
    __syncthreads();
    for (int off = 128; off > 0; off >>= 1) {
        if (threadIdx.x < off) s[threadIdx.x] += s[threadIdx.x + off];
        __syncthreads();
    }
    if (threadIdx.x == 0 && write_loss) out[BCT] = 1.25f * s[0] / 16777216.f;
}

// ---------------------------------------------------------------------------
extern "C" void kernel_launch(void* const* d_in, const int* in_sizes, int n_in,
                              void* d_out, int out_size) {
    const float* x  = (const float*)d_in[0];
    const float* cb = (const float*)d_in[1];
    float* out = (float*)d_out;
    const long long expected = (long long)BCT + 1 + NROWS;
    int write_aux = (out_size >= expected) ? 1 : 0;

    static int attr_set = 0;
    const int out_smem = (CC * QTP + 8 + 64) * 4;   // 67,168 B
    if (!attr_set) {
        cudaFuncSetAttribute(vq_cand, cudaFuncAttributeMaxDynamicSharedMemorySize, SM_TOT);
        cudaFuncSetAttribute(vq_out,  cudaFuncAttributeMaxDynamicSharedMemorySize, out_smem);
        attr_set = 1;
    }

    vq_prep<<<256, 256>>>(cb);
    vq_cand<<<512, 512, SM_TOT>>>(x);
    vq_rescore<<<128, 128>>>(x, cb);
    vq_out<<<dim3(64, 16), 256, out_smem>>>(x, cb, out, write_aux);
    vq_finalize<<<1, 256>>>(out, write_aux);
}